// round 2
// baseline (speedup 1.0000x reference)
#include <cuda_runtime.h>
#include <math.h>

// Problem constants
#define B_   2
#define L_   2048
#define T_   4096        // B_*L_
#define DM_  1024
#define DI_  2048
#define DS_  16
#define DC_  4
#define DTR_ 64
#define V_   32000
#define DBC_ 96          // DTR + 2*DS

// ---------------- scratch (device globals; no allocation allowed) ----------------
__device__ float g_emb[T_ * DM_];        // 16 MB
__device__ float g_xz [T_ * 2 * DI_];    // 64 MB  (x = [:,0:2048], z = [:,2048:4096])
__device__ float g_x  [T_ * DI_];        // 32 MB  post conv+silu
__device__ float g_dbc[T_ * DBC_];       // dt_raw | B | C
__device__ float g_dt [T_ * DI_];        // 32 MB  softplus(dt)
__device__ float g_y  [T_ * DI_];        // 32 MB  scan output, then gated in-place
__device__ float g_y2 [T_ * DM_];        // 16 MB  out_proj output

// ---------------- helpers ----------------
__device__ __forceinline__ float softplusf(float x) {
    return fmaxf(x, 0.f) + log1pf(__expf(-fabsf(x)));
}
__device__ __forceinline__ float siluf(float x) {
    return x / (1.f + __expf(-x));
}

// Source selector so GEMM kernels can address __device__ globals without any
// host-side symbol lookup.
enum Buf { BUF_EMB = 0, BUF_XZ, BUF_X, BUF_DBC, BUF_DT, BUF_Y, BUF_Y2, BUF_EXT };

__device__ __forceinline__ const float* buf_ptr(int sel, const float* ext) {
    switch (sel) {
        case BUF_EMB: return g_emb;
        case BUF_XZ:  return g_xz;
        case BUF_X:   return g_x;
        case BUF_DBC: return g_dbc;
        case BUF_DT:  return g_dt;
        case BUF_Y:   return g_y;
        case BUF_Y2:  return g_y2;
        default:      return ext;
    }
}
__device__ __forceinline__ float* buf_ptr_mut(int sel, float* ext) {
    switch (sel) {
        case BUF_EMB: return g_emb;
        case BUF_XZ:  return g_xz;
        case BUF_X:   return g_x;
        case BUF_DBC: return g_dbc;
        case BUF_DT:  return g_dt;
        case BUF_Y:   return g_y;
        case BUF_Y2:  return g_y2;
        default:      return ext;
    }
}

// ---------------- embedding gather (float4) ----------------
__global__ void gather_kernel(const int* __restrict__ tokens,
                              const float* __restrict__ embed) {
    int i = blockIdx.x * blockDim.x + threadIdx.x;   // over T_*DM_/4
    int t = i >> 8;                                  // DM_/4 = 256
    int j = i & 255;
    int tok = tokens[t];
    reinterpret_cast<float4*>(g_emb)[t * 256 + j] =
        reinterpret_cast<const float4*>(embed)[tok * 256 + j];
}

// ---------------- causal depthwise conv (DC=4) + bias + SiLU ----------------
__global__ void conv_silu_kernel(const float* __restrict__ cw,
                                 const float* __restrict__ cb) {
    int i = blockIdx.x * blockDim.x + threadIdx.x;   // over T_*DI_
    int c = i & (DI_ - 1);
    int t = i >> 11;                                 // DI_=2048
    int l = t & (L_ - 1);
    float acc = cb[c];
#pragma unroll
    for (int k = 0; k < DC_; k++) {
        int ll = l - (DC_ - 1) + k;
        if (ll >= 0)
            acc = fmaf(cw[c * DC_ + k], g_xz[(size_t)(t - (DC_ - 1) + k) * (2 * DI_) + c], acc);
    }
    g_x[i] = siluf(acc);
}

// ---------------- selective scan ----------------
// grid (DI_/32, B_), block 512.  thread = (d_local, s): tid = d_local*16 + s
__global__ void scan_kernel(const float* __restrict__ A_log) {
    int s  = threadIdx.x & 15;
    int dl = threadIdx.x >> 4;
    int d  = blockIdx.x * 32 + dl;
    int b  = blockIdx.y;

    float a = -__expf(A_log[d * DS_ + s]);
    float h = 0.f;

    int t0 = b * L_;
    const float* dtp = g_dt  + (size_t)t0 * DI_ + d;
    const float* up  = g_x   + (size_t)t0 * DI_ + d;
    const float* bp  = g_dbc + (size_t)t0 * DBC_ + DTR_ + s;
    const float* cp  = bp + DS_;
    float*       yp  = g_y   + (size_t)t0 * DI_ + d;

    for (int l = 0; l < L_; l++) {
        float dtv = *dtp;
        float uv  = *up;
        float Bv  = *bp;
        float Cv  = *cp;
        float dA = __expf(dtv * a);
        h = fmaf(dA, h, dtv * Bv * uv);
        float p = h * Cv;
        p += __shfl_xor_sync(0xffffffffu, p, 1);
        p += __shfl_xor_sync(0xffffffffu, p, 2);
        p += __shfl_xor_sync(0xffffffffu, p, 4);
        p += __shfl_xor_sync(0xffffffffu, p, 8);
        if (s == 0) *yp = p;
        dtp += DI_; up += DI_; bp += DBC_; cp += DBC_; yp += DI_;
    }
}

// ---------------- gating (in-place): y = (y + x*D) * silu(z) ----------------
__global__ void gate_kernel(const float* __restrict__ Dv) {
    int i = blockIdx.x * blockDim.x + threadIdx.x;   // over T_*DI_
    int d = i & (DI_ - 1);
    int t = i >> 11;
    float z = g_xz[(size_t)t * (2 * DI_) + DI_ + d];
    g_y[i] = (g_y[i] + g_x[i] * Dv[d]) * siluf(z);
}

// ---------------- generic NT GEMM:  C[M,N] = A[M,K(lda)] * W[N,K]^T ----------------
// A row stride = lda, W row stride = K, C row stride = N. K % BK == 0, M % BM == 0.
// EPI: 0=none, 1=+bias, 2=softplus(+bias)
// a_sel / c_sel pick __device__ global scratch buffers (BUF_EXT -> use pointer arg).
template<int BM, int BN, int BK, int TM, int TN, int EPI>
__global__ __launch_bounds__((BM / TM) * (BN / TN))
void gemm_nt(int a_sel, const float* __restrict__ A_ext, int lda,
             const float* __restrict__ W,
             const float* __restrict__ bias,
             int c_sel, float* __restrict__ C_ext,
             int M, int N, int K) {
    const float* __restrict__ A = buf_ptr(a_sel, A_ext);
    float* __restrict__ C = buf_ptr_mut(c_sel, C_ext);

    constexpr int THREADS = (BM / TM) * (BN / TN);
    constexpr int K4 = BK / 4;
    __shared__ float As[BK][BM + 4];
    __shared__ float Ws[BK][BN + 4];

    const int tid = threadIdx.x;
    const int bm = blockIdx.y * BM;
    const int bn = blockIdx.x * BN;
    const int tx = tid % (BN / TN);
    const int ty = tid / (BN / TN);

    float acc[TM][TN];
#pragma unroll
    for (int i = 0; i < TM; i++)
#pragma unroll
        for (int j = 0; j < TN; j++) acc[i][j] = 0.f;

    for (int k0 = 0; k0 < K; k0 += BK) {
        // load A tile (transposed into As[k][m])
#pragma unroll
        for (int i = tid; i < BM * K4; i += THREADS) {
            int r = i / K4, kk = (i % K4) * 4;
            float4 v = *reinterpret_cast<const float4*>(
                &A[(size_t)(bm + r) * lda + k0 + kk]);
            As[kk + 0][r] = v.x; As[kk + 1][r] = v.y;
            As[kk + 2][r] = v.z; As[kk + 3][r] = v.w;
        }
        // load W tile (transposed into Ws[k][n]) with N guard
#pragma unroll
        for (int i = tid; i < BN * K4; i += THREADS) {
            int r = i / K4, kk = (i % K4) * 4;
            float4 v = make_float4(0.f, 0.f, 0.f, 0.f);
            if (bn + r < N)
                v = *reinterpret_cast<const float4*>(
                    &W[(size_t)(bn + r) * K + k0 + kk]);
            Ws[kk + 0][r] = v.x; Ws[kk + 1][r] = v.y;
            Ws[kk + 2][r] = v.z; Ws[kk + 3][r] = v.w;
        }
        __syncthreads();

#pragma unroll
        for (int k = 0; k < BK; k++) {
            float a[TM], b[TN];
#pragma unroll
            for (int i = 0; i < TM; i++) a[i] = As[k][ty * TM + i];
#pragma unroll
            for (int j = 0; j < TN; j++) b[j] = Ws[k][tx * TN + j];
#pragma unroll
            for (int i = 0; i < TM; i++)
#pragma unroll
                for (int j = 0; j < TN; j++)
                    acc[i][j] = fmaf(a[i], b[j], acc[i][j]);
        }
        __syncthreads();
    }

#pragma unroll
    for (int i = 0; i < TM; i++) {
        int row = bm + ty * TM + i;
#pragma unroll
        for (int j = 0; j < TN; j++) {
            int col = bn + tx * TN + j;
            if (col < N) {
                float v = acc[i][j];
                if (EPI >= 1) v += bias[col];
                if (EPI == 2) v = softplusf(v);
                C[(size_t)row * N + col] = v;
            }
        }
    }
}

// ---------------- launch ----------------
extern "C" void kernel_launch(void* const* d_in, const int* in_sizes, int n_in,
                              void* d_out, int out_size) {
    const int*   tokens     = (const int*)  d_in[0];
    const float* embed      = (const float*)d_in[1];
    const float* in_proj_w  = (const float*)d_in[2];
    const float* conv_w     = (const float*)d_in[3];
    const float* conv_b     = (const float*)d_in[4];
    const float* x_proj_w   = (const float*)d_in[5];
    const float* dt_proj_w  = (const float*)d_in[6];
    const float* dt_proj_b  = (const float*)d_in[7];
    const float* A_log      = (const float*)d_in[8];
    const float* Dv         = (const float*)d_in[9];
    const float* out_proj_w = (const float*)d_in[10];
    const float* head_w     = (const float*)d_in[11];
    const float* head_b     = (const float*)d_in[12];
    float* out = (float*)d_out;

    // 1. embedding gather
    gather_kernel<<<(T_ * DM_ / 4) / 256, 256>>>(tokens, embed);

    // 2. in_proj: xz[T,4096] = emb[T,1024] @ in_proj_w[4096,1024]^T
    gemm_nt<128, 128, 16, 8, 8, 0><<<dim3(2 * DI_ / 128, T_ / 128), 256>>>(
        BUF_EMB, nullptr, DM_, in_proj_w, nullptr, BUF_XZ, nullptr,
        T_, 2 * DI_, DM_);

    // 3. causal conv + SiLU
    conv_silu_kernel<<<(T_ * DI_) / 256, 256>>>(conv_w, conv_b);

    // 4. x_proj: dbc[T,96] = x[T,2048] @ x_proj_w[96,2048]^T
    gemm_nt<64, 64, 16, 4, 4, 0><<<dim3((DBC_ + 63) / 64, T_ / 64), 256>>>(
        BUF_X, nullptr, DI_, x_proj_w, nullptr, BUF_DBC, nullptr,
        T_, DBC_, DI_);

    // 5. dt: dt[T,2048] = softplus(dbc[:, :64] @ dt_proj_w[2048,64]^T + dt_proj_b)
    gemm_nt<128, 128, 16, 8, 8, 2><<<dim3(DI_ / 128, T_ / 128), 256>>>(
        BUF_DBC, nullptr, DBC_, dt_proj_w, dt_proj_b, BUF_DT, nullptr,
        T_, DI_, DTR_);

    // 6. selective scan -> g_y
    scan_kernel<<<dim3(DI_ / 32, B_), 512>>>(A_log);

    // 7. gating in-place on g_y
    gate_kernel<<<(T_ * DI_) / 256, 256>>>(Dv);

    // 8. out_proj: y2[T,1024] = y[T,2048] @ out_proj_w[1024,2048]^T
    gemm_nt<128, 128, 16, 8, 8, 0><<<dim3(DM_ / 128, T_ / 128), 256>>>(
        BUF_Y, nullptr, DI_, out_proj_w, nullptr, BUF_Y2, nullptr,
        T_, DM_, DI_);

    // 9. head: out[T,32000] = y2[T,1024] @ head_w[32000,1024]^T + head_b
    gemm_nt<128, 128, 16, 8, 8, 1><<<dim3(V_ / 128, T_ / 128), 256>>>(
        BUF_Y2, nullptr, DM_, head_w, head_b, BUF_EXT, out,
        T_, V_, DM_);
}

// round 5
// speedup vs baseline: 2.0549x; 2.0549x over previous
#include <cuda_runtime.h>
#include <cuda_bf16.h>
#include <cstdint>
#include <math.h>

// Problem constants
#define B_   2
#define L_   2048
#define T_   4096        // B_*L_
#define DM_  1024
#define DI_  2048
#define DS_  16
#define DC_  4
#define DTR_ 64
#define V_   32000
#define DBC_ 96          // DTR + 2*DS

// ---------------- fp32 scratch ----------------
__device__ float g_emb[T_ * DM_];
__device__ float g_xz [T_ * 2 * DI_];    // x | z
__device__ float g_x  [T_ * DI_];
__device__ float g_dbc[T_ * DBC_];
__device__ float g_dt [T_ * DI_];
__device__ float g_y  [T_ * DI_];
__device__ float g_y2 [T_ * DM_];

// ---------------- bf16 split scratch (hi/lo) ----------------
__device__ __nv_bfloat16 g_aemb_h[T_ * DM_],  g_aemb_l[T_ * DM_];
__device__ __nv_bfloat16 g_adt_h [T_ * DTR_], g_adt_l [T_ * DTR_];
__device__ __nv_bfloat16 g_ay_h  [T_ * DI_],  g_ay_l  [T_ * DI_];
__device__ __nv_bfloat16 g_ay2_h [T_ * DM_],  g_ay2_l [T_ * DM_];
__device__ __nv_bfloat16 g_win_h [2*DI_*DM_], g_win_l [2*DI_*DM_];
__device__ __nv_bfloat16 g_wdt_h [DI_*DTR_],  g_wdt_l [DI_*DTR_];
__device__ __nv_bfloat16 g_wout_h[DM_*DI_],   g_wout_l[DM_*DI_];
__device__ __nv_bfloat16 g_whead_h[(size_t)V_*DM_], g_whead_l[(size_t)V_*DM_];

// ---------------- selectors ----------------
enum Buf   { BUF_EMB = 0, BUF_XZ, BUF_X, BUF_DBC, BUF_DT, BUF_Y, BUF_Y2, BUF_EXT };
enum BPair { P_AEMB = 0, P_ADT, P_AY, P_AY2, P_WIN, P_WDT, P_WOUT, P_WHEAD };

__device__ __forceinline__ const float* buf_ptr(int sel, const float* ext) {
    switch (sel) {
        case BUF_EMB: return g_emb;  case BUF_XZ: return g_xz;
        case BUF_X:   return g_x;    case BUF_DBC: return g_dbc;
        case BUF_DT:  return g_dt;   case BUF_Y:  return g_y;
        case BUF_Y2:  return g_y2;   default:     return ext;
    }
}
__device__ __forceinline__ float* buf_ptr_mut(int sel, float* ext) {
    switch (sel) {
        case BUF_EMB: return g_emb;  case BUF_XZ: return g_xz;
        case BUF_X:   return g_x;    case BUF_DBC: return g_dbc;
        case BUF_DT:  return g_dt;   case BUF_Y:  return g_y;
        case BUF_Y2:  return g_y2;   default:     return ext;
    }
}
__device__ __forceinline__ void bpair(int sel, __nv_bfloat16*& h, __nv_bfloat16*& l) {
    switch (sel) {
        case P_AEMB: h = g_aemb_h;  l = g_aemb_l;  break;
        case P_ADT:  h = g_adt_h;   l = g_adt_l;   break;
        case P_AY:   h = g_ay_h;    l = g_ay_l;    break;
        case P_AY2:  h = g_ay2_h;   l = g_ay2_l;   break;
        case P_WIN:  h = g_win_h;   l = g_win_l;   break;
        case P_WDT:  h = g_wdt_h;   l = g_wdt_l;   break;
        case P_WOUT: h = g_wout_h;  l = g_wout_l;  break;
        default:     h = g_whead_h; l = g_whead_l; break;
    }
}

// ---------------- math helpers ----------------
__device__ __forceinline__ float softplusf(float x) {
    return fmaxf(x, 0.f) + log1pf(__expf(-fabsf(x)));
}
__device__ __forceinline__ float siluf(float x) {
    return x / (1.f + __expf(-x));
}
__device__ __forceinline__ uint32_t smem_u32(const void* p) {
    uint32_t a;
    asm("{ .reg .u64 t; cvta.to.shared.u64 t, %1; cvt.u32.u64 %0, t; }" : "=r"(a) : "l"(p));
    return a;
}
__device__ __forceinline__ void cp16(uint32_t saddr, const void* g) {
    asm volatile("cp.async.cg.shared.global [%0], [%1], 16;" :: "r"(saddr), "l"(g));
}
__device__ __forceinline__ void ldsm4(uint32_t* r, uint32_t addr) {
    asm volatile("ldmatrix.sync.aligned.m8n8.x4.shared.b16 {%0,%1,%2,%3}, [%4];"
        : "=r"(r[0]), "=r"(r[1]), "=r"(r[2]), "=r"(r[3]) : "r"(addr));
}
__device__ __forceinline__ void mma16816(float* c, const uint32_t* a, uint32_t b0, uint32_t b1) {
    asm volatile("mma.sync.aligned.m16n8k16.row.col.f32.bf16.bf16.f32 "
        "{%0,%1,%2,%3}, {%4,%5,%6,%7}, {%8,%9}, {%0,%1,%2,%3};"
        : "+f"(c[0]), "+f"(c[1]), "+f"(c[2]), "+f"(c[3])
        : "r"(a[0]), "r"(a[1]), "r"(a[2]), "r"(a[3]), "r"(b0), "r"(b1));
}

// ---------------- elementwise kernels ----------------
__global__ void gather_kernel(const int* __restrict__ tokens,
                              const float* __restrict__ embed) {
    int i = blockIdx.x * blockDim.x + threadIdx.x;
    int t = i >> 8, j = i & 255;
    int tok = tokens[t];
    reinterpret_cast<float4*>(g_emb)[t * 256 + j] =
        reinterpret_cast<const float4*>(embed)[tok * 256 + j];
}

__device__ __forceinline__ void split1(float x, __nv_bfloat16& h, __nv_bfloat16& l) {
    h = __float2bfloat16(x);
    l = __float2bfloat16(x - __bfloat162float(h));
}

__global__ void split_kernel(int src_sel, const float* __restrict__ ext, int dst_sel, int n4) {
    int i = blockIdx.x * blockDim.x + threadIdx.x;
    if (i >= n4) return;
    const float* src = buf_ptr(src_sel, ext);
    __nv_bfloat16 *dh, *dl; bpair(dst_sel, dh, dl);
    float4 v = reinterpret_cast<const float4*>(src)[i];
    __nv_bfloat16 h0, l0, h1, l1, h2, l2, h3, l3;
    split1(v.x, h0, l0); split1(v.y, h1, l1);
    split1(v.z, h2, l2); split1(v.w, h3, l3);
    reinterpret_cast<__nv_bfloat162*>(dh)[2*i]   = __nv_bfloat162(h0, h1);
    reinterpret_cast<__nv_bfloat162*>(dh)[2*i+1] = __nv_bfloat162(h2, h3);
    reinterpret_cast<__nv_bfloat162*>(dl)[2*i]   = __nv_bfloat162(l0, l1);
    reinterpret_cast<__nv_bfloat162*>(dl)[2*i+1] = __nv_bfloat162(l2, l3);
}

// extract first 64 cols of g_dbc (stride 96) -> a_dt hi/lo
__global__ void split_dt_kernel() {
    int i = blockIdx.x * blockDim.x + threadIdx.x;   // over T_*16
    if (i >= T_ * 16) return;
    int t = i >> 4, c = (i & 15) * 4;
    float4 v = *reinterpret_cast<const float4*>(&g_dbc[(size_t)t * DBC_ + c]);
    __nv_bfloat16 h0, l0, h1, l1, h2, l2, h3, l3;
    split1(v.x, h0, l0); split1(v.y, h1, l1);
    split1(v.z, h2, l2); split1(v.w, h3, l3);
    size_t o = ((size_t)t * DTR_ + c) >> 1;
    reinterpret_cast<__nv_bfloat162*>(g_adt_h)[o]   = __nv_bfloat162(h0, h1);
    reinterpret_cast<__nv_bfloat162*>(g_adt_h)[o+1] = __nv_bfloat162(h2, h3);
    reinterpret_cast<__nv_bfloat162*>(g_adt_l)[o]   = __nv_bfloat162(l0, l1);
    reinterpret_cast<__nv_bfloat162*>(g_adt_l)[o+1] = __nv_bfloat162(l2, l3);
}

__global__ void conv_silu_kernel(const float* __restrict__ cw,
                                 const float* __restrict__ cb) {
    int i = blockIdx.x * blockDim.x + threadIdx.x;
    int c = i & (DI_ - 1);
    int t = i >> 11;
    int l = t & (L_ - 1);
    float acc = cb[c];
#pragma unroll
    for (int k = 0; k < DC_; k++) {
        int ll = l - (DC_ - 1) + k;
        if (ll >= 0)
            acc = fmaf(cw[c * DC_ + k], g_xz[(size_t)(t - (DC_ - 1) + k) * (2 * DI_) + c], acc);
    }
    g_x[i] = siluf(acc);
}

__global__ void scan_kernel(const float* __restrict__ A_log) {
    int s  = threadIdx.x & 15;
    int dl = threadIdx.x >> 4;
    int d  = blockIdx.x * 32 + dl;
    int b  = blockIdx.y;
    float a = -__expf(A_log[d * DS_ + s]);
    float h = 0.f;
    int t0 = b * L_;
    const float* dtp = g_dt  + (size_t)t0 * DI_ + d;
    const float* up  = g_x   + (size_t)t0 * DI_ + d;
    const float* bp  = g_dbc + (size_t)t0 * DBC_ + DTR_ + s;
    const float* cp  = bp + DS_;
    float*       yp  = g_y   + (size_t)t0 * DI_ + d;
    for (int l = 0; l < L_; l++) {
        float dtv = *dtp, uv = *up, Bv = *bp, Cv = *cp;
        float dA = __expf(dtv * a);
        h = fmaf(dA, h, dtv * Bv * uv);
        float p = h * Cv;
        p += __shfl_xor_sync(0xffffffffu, p, 1);
        p += __shfl_xor_sync(0xffffffffu, p, 2);
        p += __shfl_xor_sync(0xffffffffu, p, 4);
        p += __shfl_xor_sync(0xffffffffu, p, 8);
        if (s == 0) *yp = p;
        dtp += DI_; up += DI_; bp += DBC_; cp += DBC_; yp += DI_;
    }
}

__global__ void gate_kernel(const float* __restrict__ Dv) {
    int i = blockIdx.x * blockDim.x + threadIdx.x;
    int d = i & (DI_ - 1);
    int t = i >> 11;
    float z = g_xz[(size_t)t * (2 * DI_) + DI_ + d];
    g_y[i] = (g_y[i] + g_x[i] * Dv[d]) * siluf(z);
}

// ---------------- fp32 SIMT GEMM (x_proj only, N=96) ----------------
template<int BM, int BN, int BK, int TM, int TN>
__global__ __launch_bounds__((BM / TM) * (BN / TN))
void gemm_nt(int a_sel, int lda, const float* __restrict__ W,
             int c_sel, int M, int N, int K) {
    const float* __restrict__ A = buf_ptr(a_sel, nullptr);
    float* __restrict__ C = buf_ptr_mut(c_sel, nullptr);
    constexpr int THREADS = (BM / TM) * (BN / TN);
    constexpr int K4 = BK / 4;
    __shared__ float As[BK][BM + 4];
    __shared__ float Ws[BK][BN + 4];
    const int tid = threadIdx.x;
    const int bm = blockIdx.y * BM;
    const int bn = blockIdx.x * BN;
    const int tx = tid % (BN / TN);
    const int ty = tid / (BN / TN);
    float acc[TM][TN];
#pragma unroll
    for (int i = 0; i < TM; i++)
#pragma unroll
        for (int j = 0; j < TN; j++) acc[i][j] = 0.f;
    for (int k0 = 0; k0 < K; k0 += BK) {
#pragma unroll
        for (int i = tid; i < BM * K4; i += THREADS) {
            int r = i / K4, kk = (i % K4) * 4;
            float4 v = *reinterpret_cast<const float4*>(&A[(size_t)(bm + r) * lda + k0 + kk]);
            As[kk+0][r] = v.x; As[kk+1][r] = v.y; As[kk+2][r] = v.z; As[kk+3][r] = v.w;
        }
#pragma unroll
        for (int i = tid; i < BN * K4; i += THREADS) {
            int r = i / K4, kk = (i % K4) * 4;
            float4 v = make_float4(0.f, 0.f, 0.f, 0.f);
            if (bn + r < N)
                v = *reinterpret_cast<const float4*>(&W[(size_t)(bn + r) * K + k0 + kk]);
            Ws[kk+0][r] = v.x; Ws[kk+1][r] = v.y; Ws[kk+2][r] = v.z; Ws[kk+3][r] = v.w;
        }
        __syncthreads();
#pragma unroll
        for (int k = 0; k < BK; k++) {
            float a[TM], b[TN];
#pragma unroll
            for (int i = 0; i < TM; i++) a[i] = As[k][ty * TM + i];
#pragma unroll
            for (int j = 0; j < TN; j++) b[j] = Ws[k][tx * TN + j];
#pragma unroll
            for (int i = 0; i < TM; i++)
#pragma unroll
                for (int j = 0; j < TN; j++) acc[i][j] = fmaf(a[i], b[j], acc[i][j]);
        }
        __syncthreads();
    }
#pragma unroll
    for (int i = 0; i < TM; i++) {
        int row = bm + ty * TM + i;
#pragma unroll
        for (int j = 0; j < TN; j++) {
            int col = bn + tx * TN + j;
            if (col < N) C[(size_t)row * N + col] = acc[i][j];
        }
    }
}

// ---------------- HMMA split-bf16 GEMM (mma.sync m16n8k16) ----------------
// C[M,N] = (Ah+Al)[M,K] @ ((Bh+Bl)[N,K])^T, 3-product split, fp32 accum.
// Tile 128x128xBK32, 256 threads = 8 warps, warp tile 32x64.
// Requires M%128==0, N%128==0, K%32==0.
#define LDSg 40                            // 32 + 8 bf16 pad (conflict-free ldmatrix)
#define AH_OFF 0
#define AL_OFF (128 * LDSg)
#define BH_OFF (2 * 128 * LDSg)
#define BL_OFF (3 * 128 * LDSg)
#define STAGE_BF16 (4 * 128 * LDSg)        // 20480 bf16
#define STAGE_B (STAGE_BF16 * 2)           // 40960 bytes
#define SMEM_MMA (2 * STAGE_B)             // 81920 bytes

__global__ __launch_bounds__(256)
void gemm_mma(int a_sel, int b_sel, int c_sel, float* __restrict__ C_ext,
              const float* __restrict__ bias, int M, int N, int K, int epi) {
    extern __shared__ __nv_bfloat16 sm[];
    __nv_bfloat16 *Ah, *Al, *Bh, *Bl;
    bpair(a_sel, Ah, Al);
    bpair(b_sel, Bh, Bl);
    float* __restrict__ C = buf_ptr_mut(c_sel, C_ext);

    const int tid  = threadIdx.x;
    const int wid  = tid >> 5, lane = tid & 31;
    const int bm   = blockIdx.x * 128;          // x = M-tile (fast) -> W streamed once
    const int bn   = blockIdx.y * 128;
    const int wm   = wid & 3;                   // 4 m-warps of 32 rows
    const int wn   = wid >> 2;                  // 2 n-warps of 64 cols
    const int KT   = K >> 5;

    const uint32_t sb0 = smem_u32(sm);

    auto load_stage = [&](int st, int kt) {
        const int k0 = kt * 32;
        const uint32_t sb = sb0 + st * STAGE_B;
#pragma unroll
        for (int ii = 0; ii < 8; ii++) {
            int i   = tid + ii * 256;
            int arr = i >> 9;                   // 0=Ah 1=Al 2=Bh 3=Bl
            int r   = (i >> 2) & 127;
            int c   = (i & 3) * 8;
            const __nv_bfloat16* src = (arr == 0) ? Ah : (arr == 1) ? Al
                                     : (arr == 2) ? Bh : Bl;
            int grow = (arr < 2 ? bm : bn) + r;
            cp16(sb + (uint32_t)(arr * 128 * LDSg + r * LDSg + c) * 2,
                 src + (size_t)grow * K + k0 + c);
        }
    };

    float acc[2][8][4];
#pragma unroll
    for (int i = 0; i < 2; i++)
#pragma unroll
        for (int j = 0; j < 8; j++)
#pragma unroll
            for (int k = 0; k < 4; k++) acc[i][j][k] = 0.f;

    // prologue
    load_stage(0, 0);
    asm volatile("cp.async.commit_group;" ::: "memory");
    if (KT > 1) load_stage(1, 1);
    asm volatile("cp.async.commit_group;" ::: "memory");

    // per-thread ldmatrix address components
    const int a_r = (lane & 15);                // row within 16
    const int a_c = ((lane >> 4) << 3);         // 0 or 8
    const int b_r = ((lane >> 3) & 1) * 8 + (lane & 7);  // row within 16
    const int b_c = ((lane >> 4) << 3);

    for (int kt = 0; kt < KT; kt++) {
        const int st = kt & 1;
        asm volatile("cp.async.wait_group 1;" ::: "memory");
        __syncthreads();
        const uint32_t sb = sb0 + st * STAGE_B;

#pragma unroll
        for (int k16 = 0; k16 < 32; k16 += 16) {
            uint32_t ah[2][4], al[2][4];
#pragma unroll
            for (int mt = 0; mt < 2; mt++) {
                int row = wm * 32 + mt * 16 + a_r;
                uint32_t off = (uint32_t)(row * LDSg + k16 + a_c) * 2;
                ldsm4(ah[mt], sb + AH_OFF * 2 + off);
                ldsm4(al[mt], sb + AL_OFF * 2 + off);
            }
#pragma unroll
            for (int nt2 = 0; nt2 < 4; nt2++) {
                int row = wn * 64 + nt2 * 16 + b_r;
                uint32_t off = (uint32_t)(row * LDSg + k16 + b_c) * 2;
                uint32_t bh[4], bl[4];
                ldsm4(bh, sb + BH_OFF * 2 + off);
                ldsm4(bl, sb + BL_OFF * 2 + off);
                // bh: r0=(n lo,k lo) r1=(n hi,k lo) r2=(n lo,k hi) r3=(n hi,k hi)
#pragma unroll
                for (int mt = 0; mt < 2; mt++) {
                    float* c0 = acc[mt][nt2 * 2];
                    float* c1 = acc[mt][nt2 * 2 + 1];
                    mma16816(c0, ah[mt], bh[0], bh[2]);
                    mma16816(c0, ah[mt], bl[0], bl[2]);
                    mma16816(c0, al[mt], bh[0], bh[2]);
                    mma16816(c1, ah[mt], bh[1], bh[3]);
                    mma16816(c1, ah[mt], bl[1], bl[3]);
                    mma16816(c1, al[mt], bh[1], bh[3]);
                }
            }
        }
        __syncthreads();
        if (kt + 2 < KT) load_stage(st, kt + 2);
        asm volatile("cp.async.commit_group;" ::: "memory");
    }

    // epilogue: frag (mt,nt): rows bm+wm*32+mt*16 + {lane/4, lane/4+8},
    //                         cols bn+wn*64+nt*8 + (lane%4)*2 + {0,1}
    const int er = bm + wm * 32 + (lane >> 2);
    const int ec = bn + wn * 64 + (lane & 3) * 2;
#pragma unroll
    for (int mt = 0; mt < 2; mt++) {
#pragma unroll
        for (int nt = 0; nt < 8; nt++) {
            int col = ec + nt * 8;
            float b0 = 0.f, b1 = 0.f;
            if (epi >= 1) { b0 = bias[col]; b1 = bias[col + 1]; }
#pragma unroll
            for (int half = 0; half < 2; half++) {
                int row = er + mt * 16 + half * 8;
                float v0 = acc[mt][nt][half * 2 + 0] + b0;
                float v1 = acc[mt][nt][half * 2 + 1] + b1;
                if (epi == 2) { v0 = softplusf(v0); v1 = softplusf(v1); }
                *reinterpret_cast<float2*>(&C[(size_t)row * N + col]) =
                    make_float2(v0, v1);
            }
        }
    }
}

// ---------------- launch ----------------
extern "C" void kernel_launch(void* const* d_in, const int* in_sizes, int n_in,
                              void* d_out, int out_size) {
    const int*   tokens     = (const int*)  d_in[0];
    const float* embed      = (const float*)d_in[1];
    const float* in_proj_w  = (const float*)d_in[2];
    const float* conv_w     = (const float*)d_in[3];
    const float* conv_b     = (const float*)d_in[4];
    const float* x_proj_w   = (const float*)d_in[5];
    const float* dt_proj_w  = (const float*)d_in[6];
    const float* dt_proj_b  = (const float*)d_in[7];
    const float* A_log      = (const float*)d_in[8];
    const float* Dv         = (const float*)d_in[9];
    const float* out_proj_w = (const float*)d_in[10];
    const float* head_w     = (const float*)d_in[11];
    const float* head_b     = (const float*)d_in[12];
    float* out = (float*)d_out;

    cudaFuncSetAttribute(gemm_mma, cudaFuncAttributeMaxDynamicSharedMemorySize, SMEM_MMA);

    // weight splits
    split_kernel<<<(2*DI_*DM_/4 + 255)/256, 256>>>(BUF_EXT, in_proj_w,  P_WIN,  2*DI_*DM_/4);
    split_kernel<<<(DI_*DTR_/4  + 255)/256, 256>>>(BUF_EXT, dt_proj_w,  P_WDT,  DI_*DTR_/4);
    split_kernel<<<(DM_*DI_/4   + 255)/256, 256>>>(BUF_EXT, out_proj_w, P_WOUT, DM_*DI_/4);
    split_kernel<<<(V_*DM_/4    + 255)/256, 256>>>(BUF_EXT, head_w,     P_WHEAD, V_*DM_/4);

    // 1. embedding gather + split
    gather_kernel<<<(T_ * DM_ / 4) / 256, 256>>>(tokens, embed);
    split_kernel<<<(T_*DM_/4 + 255)/256, 256>>>(BUF_EMB, nullptr, P_AEMB, T_*DM_/4);

    // 2. in_proj (HMMA): xz[T,4096] = emb @ in_proj_w^T
    gemm_mma<<<dim3(T_/128, 2*DI_/128), 256, SMEM_MMA>>>(
        P_AEMB, P_WIN, BUF_XZ, nullptr, nullptr, T_, 2*DI_, DM_, 0);

    // 3. causal conv + SiLU
    conv_silu_kernel<<<(T_ * DI_) / 256, 256>>>(conv_w, conv_b);

    // 4. x_proj (fp32 SIMT, N=96): dbc = x @ x_proj_w^T
    gemm_nt<64, 64, 16, 4, 4><<<dim3((DBC_ + 63)/64, T_/64), 256>>>(
        BUF_X, DI_, x_proj_w, BUF_DBC, T_, DBC_, DI_);

    // 5. dt (HMMA): dt = softplus(dbc[:, :64] @ dt_proj_w^T + b)
    split_dt_kernel<<<(T_*16 + 255)/256, 256>>>();
    gemm_mma<<<dim3(T_/128, DI_/128), 256, SMEM_MMA>>>(
        P_ADT, P_WDT, BUF_DT, nullptr, dt_proj_b, T_, DI_, DTR_, 2);

    // 6. selective scan
    scan_kernel<<<dim3(DI_/32, B_), 512>>>(A_log);

    // 7. gating in-place on g_y
    gate_kernel<<<(T_ * DI_) / 256, 256>>>(Dv);

    // 8. out_proj (HMMA): y2 = y @ out_proj_w^T
    split_kernel<<<(T_*DI_/4 + 255)/256, 256>>>(BUF_Y, nullptr, P_AY, T_*DI_/4);
    gemm_mma<<<dim3(T_/128, DM_/128), 256, SMEM_MMA>>>(
        P_AY, P_WOUT, BUF_Y2, nullptr, nullptr, T_, DM_, DI_, 0);

    // 9. head (HMMA): out = y2 @ head_w^T + head_b
    split_kernel<<<(T_*DM_/4 + 255)/256, 256>>>(BUF_Y2, nullptr, P_AY2, T_*DM_/4);
    gemm_mma<<<dim3(T_/128, V_/128), 256, SMEM_MMA>>>(
        P_AY2, P_WHEAD, BUF_EXT, out, head_b, T_, V_, DM_, 1);
}